// round 1
// baseline (speedup 1.0000x reference)
#include <cuda_runtime.h>
#include <math.h>

// ---------------- problem constants ----------------
constexpr int kB  = 2;
constexpr int kT  = 2048;
constexpr int kD  = 1024;
constexpr int kH  = 16;
constexpr int kDH = 64;
constexpr int kFF = 4096;
constexpr int kE  = 4;
constexpr int kNT = kB * kT;           // 4096 tokens
constexpr float kEPS = 1e-5f;

// ---------------- scratch (device globals: allocation-free) ----------------
__device__ float g_q[kNT * kD];
__device__ float g_k[kNT * kD];
__device__ float g_v[kNT * kD];
__device__ float g_attn[kNT * kD];
__device__ float g_proj[kNT * kD];
__device__ float g_x1[kNT * kD];
__device__ float g_y[kNT * kD];
__device__ float g_h[(size_t)kNT * kFF];   // 64 MB
__device__ int   g_cnt[kE];
__device__ int   g_list[kE * kNT];

// ---------------- generic 128x128x16 SGEMM body ----------------
// C[row][m] = sum_k A[row][k] * W[k][m] + bias[m]   (optional gather rows, relu)
__device__ __forceinline__ void gemm_body(
    const float* __restrict__ A, const float* __restrict__ W,
    const float* __restrict__ bias, float* __restrict__ C,
    int count, int K, int M, const int* __restrict__ list, bool relu)
{
    __shared__ float As[16][132];
    __shared__ float Bs[16][132];
    const int tid = threadIdx.x;                 // 256 threads
    const int rowBase = blockIdx.y * 128;
    const int colBase = blockIdx.x * 128;
    if (rowBase >= count) return;

    const int aRow = tid >> 2;                   // 0..63
    const int aCol = (tid & 3) << 2;             // 0,4,8,12
    const int bRow = tid >> 5;                   // 0..7
    const int bCol = (tid & 31) << 2;            // 0..124
    const int tRow = (tid >> 4) << 3;            // 0..120
    const int tCol = (tid & 15) << 3;            // 0..120

    const float* aptr0 = nullptr;
    const float* aptr1 = nullptr;
    {
        int r0 = rowBase + aRow;
        int r1 = rowBase + aRow + 64;
        if (r0 < count) aptr0 = A + (size_t)(list ? list[r0] : r0) * K + aCol;
        if (r1 < count) aptr1 = A + (size_t)(list ? list[r1] : r1) * K + aCol;
    }
    const float* wptr = W + (size_t)bRow * M + colBase + bCol;

    float4 a0 = aptr0 ? *(const float4*)(aptr0) : make_float4(0.f,0.f,0.f,0.f);
    float4 a1 = aptr1 ? *(const float4*)(aptr1) : make_float4(0.f,0.f,0.f,0.f);
    float4 w0 = *(const float4*)(wptr);
    float4 w1 = *(const float4*)(wptr + (size_t)8 * M);

    float acc[8][8];
    #pragma unroll
    for (int i = 0; i < 8; i++)
        #pragma unroll
        for (int j = 0; j < 8; j++) acc[i][j] = 0.f;

    for (int k0 = 0; k0 < K; k0 += 16) {
        As[aCol+0][aRow]    = a0.x; As[aCol+1][aRow]    = a0.y;
        As[aCol+2][aRow]    = a0.z; As[aCol+3][aRow]    = a0.w;
        As[aCol+0][aRow+64] = a1.x; As[aCol+1][aRow+64] = a1.y;
        As[aCol+2][aRow+64] = a1.z; As[aCol+3][aRow+64] = a1.w;
        *(float4*)&Bs[bRow][bCol]   = w0;
        *(float4*)&Bs[bRow+8][bCol] = w1;
        __syncthreads();

        int kn = k0 + 16;
        if (kn < K) {
            if (aptr0) a0 = *(const float4*)(aptr0 + kn);
            if (aptr1) a1 = *(const float4*)(aptr1 + kn);
            const float* wp = wptr + (size_t)kn * M;
            w0 = *(const float4*)(wp);
            w1 = *(const float4*)(wp + (size_t)8 * M);
        }

        #pragma unroll
        for (int kk = 0; kk < 16; kk++) {
            float ar[8], br[8];
            *(float4*)&ar[0] = *(const float4*)&As[kk][tRow];
            *(float4*)&ar[4] = *(const float4*)&As[kk][tRow + 4];
            *(float4*)&br[0] = *(const float4*)&Bs[kk][tCol];
            *(float4*)&br[4] = *(const float4*)&Bs[kk][tCol + 4];
            #pragma unroll
            for (int i = 0; i < 8; i++)
                #pragma unroll
                for (int j = 0; j < 8; j++)
                    acc[i][j] = fmaf(ar[i], br[j], acc[i][j]);
        }
        __syncthreads();
    }

    float bv[8];
    #pragma unroll
    for (int j = 0; j < 8; j++) bv[j] = bias[colBase + tCol + j];
    #pragma unroll
    for (int i = 0; i < 8; i++) {
        int lr = rowBase + tRow + i;
        if (lr < count) {
            int orow = list ? list[lr] : lr;
            float* cp = C + (size_t)orow * M + colBase + tCol;
            #pragma unroll
            for (int j = 0; j < 8; j++) {
                float v = acc[i][j] + bv[j];
                cp[j] = relu ? fmaxf(v, 0.f) : v;
            }
        }
    }
}

// ---------------- GEMM wrapper kernels ----------------
__global__ void qkv_gemm(const float* __restrict__ x,
                         const float* __restrict__ Wq, const float* __restrict__ Wk,
                         const float* __restrict__ Wv,
                         const float* __restrict__ bq, const float* __restrict__ bk,
                         const float* __restrict__ bv)
{
    int z = blockIdx.z;
    const float* W = (z == 0) ? Wq : (z == 1) ? Wk : Wv;
    const float* b = (z == 0) ? bq : (z == 1) ? bk : bv;
    float* C = (z == 0) ? g_q : (z == 1) ? g_k : g_v;
    gemm_body(x, W, b, C, kNT, kD, kD, nullptr, false);
}

__global__ void proj_gemm(const float* __restrict__ Wo, const float* __restrict__ bo)
{
    gemm_body(g_attn, Wo, bo, g_proj, kNT, kD, kD, nullptr, false);
}

__global__ void moe_gemm1(const float* __restrict__ W1e, const float* __restrict__ b1e)
{
    int e = blockIdx.z;
    gemm_body(g_x1, W1e + (size_t)e * kD * kFF, b1e + (size_t)e * kFF, g_h,
              g_cnt[e], kD, kFF, g_list + e * kNT, true);
}

__global__ void moe_gemm2(const float* __restrict__ W2e, const float* __restrict__ b2e)
{
    int e = blockIdx.z;
    gemm_body(g_h, W2e + (size_t)e * kFF * kD, b2e + (size_t)e * kD, g_y,
              g_cnt[e], kFF, kD, g_list + e * kNT, false);
}

// ---------------- flash attention (causal) ----------------
// grid: (T/64 q-tiles, B*H). 256 threads. DH=64.
constexpr int kAttnSmem = (64*68 + 64*68 + 64*64 + 64*64) * 4;   // 67584 B

__global__ void attn_kernel()
{
    extern __shared__ float sm[];
    float* Qs = sm;                      // [64 d][68]  (d-major, r index)
    float* Ks = sm + 64*68;              // [64 d][68]  (d-major, c index)
    float* Vs = sm + 2*64*68;            // [64 c][64 d]
    float* Ps = sm + 2*64*68 + 64*64;    // [64 r][64 c]

    const int tid = threadIdx.x;
    const int ty = tid >> 4;             // 0..15 -> rows 4ty..4ty+3
    const int tx = tid & 15;             // 0..15 -> cols 4tx..4tx+3
    const int bh = blockIdx.y;
    const int b = bh >> 4;
    const int h = bh & 15;
    const int qt = blockIdx.x;
    const int qbase = qt * 64;

    const float* Qg = g_q + (size_t)b * kT * kD + (size_t)h * kDH;
    const float* Kg = g_k + (size_t)b * kT * kD + (size_t)h * kDH;
    const float* Vg = g_v + (size_t)b * kT * kD + (size_t)h * kDH;

    // load Q tile transposed: Qs[d][r]
    #pragma unroll
    for (int l = 0; l < 4; l++) {
        int fid = tid + l * 256;
        int r = fid & 63;
        int d4 = fid >> 6;               // 0..15
        float4 v = *(const float4*)(Qg + (size_t)(qbase + r) * kD + d4 * 4);
        Qs[(d4*4+0)*68 + r] = v.x;
        Qs[(d4*4+1)*68 + r] = v.y;
        Qs[(d4*4+2)*68 + r] = v.z;
        Qs[(d4*4+3)*68 + r] = v.w;
    }
    __syncthreads();

    float mrow[4], lrow[4], o[4][4];
    #pragma unroll
    for (int i = 0; i < 4; i++) {
        mrow[i] = -INFINITY; lrow[i] = 0.f;
        #pragma unroll
        for (int j = 0; j < 4; j++) o[i][j] = 0.f;
    }

    for (int kt = 0; kt <= qt; kt++) {
        int kbase = kt * 64;
        // K tile transposed (scalar), V tile natural (float4)
        #pragma unroll
        for (int l = 0; l < 16; l++) {
            int idx = tid + l * 256;
            int c = idx >> 6, d = idx & 63;
            Ks[d*68 + c] = Kg[(size_t)(kbase + c) * kD + d];
        }
        #pragma unroll
        for (int l = 0; l < 4; l++) {
            int fid = tid + l * 256;
            int c = fid >> 4, d4 = fid & 15;
            *(float4*)&Vs[c*64 + d4*4] =
                *(const float4*)(Vg + (size_t)(kbase + c) * kD + d4 * 4);
        }
        __syncthreads();

        // S = Q K^T  (4x4 per thread)
        float s[4][4];
        #pragma unroll
        for (int i = 0; i < 4; i++)
            #pragma unroll
            for (int j = 0; j < 4; j++) s[i][j] = 0.f;

        #pragma unroll 8
        for (int d = 0; d < 64; d++) {
            float4 qv = *(const float4*)&Qs[d*68 + ty*4];
            float4 kv = *(const float4*)&Ks[d*68 + tx*4];
            float qa[4] = {qv.x, qv.y, qv.z, qv.w};
            float ka[4] = {kv.x, kv.y, kv.z, kv.w};
            #pragma unroll
            for (int i = 0; i < 4; i++)
                #pragma unroll
                for (int j = 0; j < 4; j++)
                    s[i][j] = fmaf(qa[i], ka[j], s[i][j]);
        }

        const bool diag = (kt == qt);
        #pragma unroll
        for (int i = 0; i < 4; i++) {
            int r = ty*4 + i;
            float sv[4];
            #pragma unroll
            for (int j = 0; j < 4; j++) {
                float val = s[i][j] * 0.125f;
                if (diag && (tx*4 + j) > r) val = -INFINITY;
                sv[j] = val;
            }
            float mp = fmaxf(fmaxf(sv[0], sv[1]), fmaxf(sv[2], sv[3]));
            #pragma unroll
            for (int o2 = 8; o2; o2 >>= 1)
                mp = fmaxf(mp, __shfl_xor_sync(0xffffffffu, mp, o2));
            float mn = fmaxf(mrow[i], mp);
            float corr = __expf(mrow[i] - mn);
            float ps = 0.f;
            #pragma unroll
            for (int j = 0; j < 4; j++) {
                float p = __expf(sv[j] - mn);
                Ps[r*64 + tx*4 + j] = p;
                ps += p;
            }
            #pragma unroll
            for (int o2 = 8; o2; o2 >>= 1)
                ps += __shfl_xor_sync(0xffffffffu, ps, o2);
            lrow[i] = lrow[i] * corr + ps;
            mrow[i] = mn;
            #pragma unroll
            for (int j = 0; j < 4; j++) o[i][j] *= corr;
        }
        __syncthreads();

        // O += P @ V
        #pragma unroll 4
        for (int c = 0; c < 64; c++) {
            float4 vv = *(const float4*)&Vs[c*64 + tx*4];
            float va[4] = {vv.x, vv.y, vv.z, vv.w};
            float pa[4];
            #pragma unroll
            for (int i = 0; i < 4; i++) pa[i] = Ps[(ty*4+i)*64 + c];
            #pragma unroll
            for (int i = 0; i < 4; i++)
                #pragma unroll
                for (int j = 0; j < 4; j++)
                    o[i][j] = fmaf(pa[i], va[j], o[i][j]);
        }
        __syncthreads();
    }

    #pragma unroll
    for (int i = 0; i < 4; i++) {
        float inv = 1.f / lrow[i];
        float* op = g_attn + (size_t)(b * kT + qbase + ty*4 + i) * kD
                    + (size_t)h * kDH + tx*4;
        #pragma unroll
        for (int j = 0; j < 4; j++) op[j] = o[i][j] * inv;
    }
}

// ---------------- add + layernorm ----------------
__device__ __forceinline__ float block_sum_256(float v, float* red)
{
    int tid = threadIdx.x;
    #pragma unroll
    for (int o = 16; o; o >>= 1) v += __shfl_xor_sync(0xffffffffu, v, o);
    if ((tid & 31) == 0) red[tid >> 5] = v;
    __syncthreads();
    if (tid < 8) {
        float x = red[tid];
        #pragma unroll
        for (int o = 4; o; o >>= 1) x += __shfl_xor_sync(0xffu, x, o);
        if (tid == 0) red[0] = x;
    }
    __syncthreads();
    float r = red[0];
    __syncthreads();
    return r;
}

__device__ __forceinline__ void add_ln_body(
    const float* __restrict__ A, const float* __restrict__ Bb,
    const float* __restrict__ gw, const float* __restrict__ bw,
    float* __restrict__ out)
{
    __shared__ float red[8];
    int t = blockIdx.x, tid = threadIdx.x;       // 256 threads, 4 floats each
    float4 av = ((const float4*)(A  + (size_t)t * kD))[tid];
    float4 bv = ((const float4*)(Bb + (size_t)t * kD))[tid];
    float vx = av.x + bv.x, vy = av.y + bv.y, vz = av.z + bv.z, vw = av.w + bv.w;
    float ssum = block_sum_256(vx + vy + vz + vw, red);
    float mu = ssum * (1.0f / kD);
    float dx = vx - mu, dy = vy - mu, dz = vz - mu, dw = vw - mu;
    float sq = block_sum_256(dx*dx + dy*dy + dz*dz + dw*dw, red);
    float rstd = rsqrtf(sq * (1.0f / kD) + kEPS);
    float4 gv = ((const float4*)gw)[tid];
    float4 be = ((const float4*)bw)[tid];
    float4 ov = make_float4(dx*rstd*gv.x + be.x, dy*rstd*gv.y + be.y,
                            dz*rstd*gv.z + be.z, dw*rstd*gv.w + be.w);
    ((float4*)(out + (size_t)t * kD))[tid] = ov;
}

__global__ void ln1_kernel(const float* __restrict__ x,
                           const float* __restrict__ g, const float* __restrict__ b)
{
    add_ln_body(x, g_proj, g, b, g_x1);
}

__global__ void ln2_kernel(const float* __restrict__ g, const float* __restrict__ b,
                           float* __restrict__ out)
{
    add_ln_body(g_x1, g_y, g, b, out);
}

// ---------------- MoE gate (top-1 argmax) ----------------
__global__ void zero_cnt()
{
    if (threadIdx.x < kE) g_cnt[threadIdx.x] = 0;
}

__global__ void gate_kernel(const float* __restrict__ Wg, const float* __restrict__ bg)
{
    int t = blockIdx.x, tid = threadIdx.x;       // 128 threads
    float a0 = 0.f, a1 = 0.f, a2 = 0.f, a3 = 0.f;
    const float* xr = g_x1 + (size_t)t * kD;
    for (int d = tid; d < kD; d += 128) {
        float xv = xr[d];
        float4 w = ((const float4*)Wg)[d];       // Wg[d][0..3]
        a0 = fmaf(xv, w.x, a0);
        a1 = fmaf(xv, w.y, a1);
        a2 = fmaf(xv, w.z, a2);
        a3 = fmaf(xv, w.w, a3);
    }
    __shared__ float rsm[4][128];
    rsm[0][tid] = a0; rsm[1][tid] = a1; rsm[2][tid] = a2; rsm[3][tid] = a3;
    __syncthreads();
    for (int s = 64; s > 0; s >>= 1) {
        if (tid < s) {
            #pragma unroll
            for (int e = 0; e < 4; e++) rsm[e][tid] += rsm[e][tid + s];
        }
        __syncthreads();
    }
    if (tid == 0) {
        float sc[4];
        #pragma unroll
        for (int e = 0; e < 4; e++) sc[e] = rsm[e][0] + bg[e];
        int best = 0; float bvv = sc[0];
        #pragma unroll
        for (int e = 1; e < 4; e++) {
            if (sc[e] > bvv) { bvv = sc[e]; best = e; }   // first-max tiebreak
        }
        int pos = atomicAdd(&g_cnt[best], 1);
        g_list[best * kNT + pos] = t;
    }
}

// ---------------- launch ----------------
extern "C" void kernel_launch(void* const* d_in, const int* in_sizes, int n_in,
                              void* d_out, int out_size)
{
    const float* x    = (const float*)d_in[0];
    // d_in[1] = mask (causal, implemented analytically)
    const float* Wq   = (const float*)d_in[2];
    const float* bq   = (const float*)d_in[3];
    const float* Wk   = (const float*)d_in[4];
    const float* bk   = (const float*)d_in[5];
    const float* Wv   = (const float*)d_in[6];
    const float* bv   = (const float*)d_in[7];
    const float* Wo   = (const float*)d_in[8];
    const float* bo   = (const float*)d_in[9];
    const float* ln1g = (const float*)d_in[10];
    const float* ln1b = (const float*)d_in[11];
    const float* Wg   = (const float*)d_in[12];
    const float* bg   = (const float*)d_in[13];
    const float* W1e  = (const float*)d_in[14];
    const float* b1e  = (const float*)d_in[15];
    const float* W2e  = (const float*)d_in[16];
    const float* b2e  = (const float*)d_in[17];
    const float* ln2g = (const float*)d_in[18];
    const float* ln2b = (const float*)d_in[19];
    float* out = (float*)d_out;

    cudaFuncSetAttribute(attn_kernel, cudaFuncAttributeMaxDynamicSharedMemorySize,
                         kAttnSmem);

    qkv_gemm<<<dim3(kD/128, kNT/128, 3), 256>>>(x, Wq, Wk, Wv, bq, bk, bv);
    attn_kernel<<<dim3(kT/64, kB*kH), 256, kAttnSmem>>>();
    proj_gemm<<<dim3(kD/128, kNT/128), 256>>>(Wo, bo);
    ln1_kernel<<<kNT, 256>>>(x, ln1g, ln1b);
    zero_cnt<<<1, 32>>>();
    gate_kernel<<<kNT, 128>>>(Wg, bg);
    moe_gemm1<<<dim3(kFF/128, kNT/128, kE), 256>>>(W1e, b1e);
    moe_gemm2<<<dim3(kD/128, kNT/128, kE), 256>>>(W2e, b2e);
    ln2_kernel<<<kNT, 256>>>(ln2g, ln2b, out);
}

// round 3
// speedup vs baseline: 1.6338x; 1.6338x over previous
#include <cuda_runtime.h>
#include <cuda_bf16.h>
#include <math.h>
#include <stdint.h>

// ---------------- problem constants ----------------
constexpr int kB  = 2;
constexpr int kT  = 2048;
constexpr int kD  = 1024;
constexpr int kH  = 16;
constexpr int kDH = 64;
constexpr int kFF = 4096;
constexpr int kE  = 4;
constexpr int kNT = kB * kT;           // 4096 tokens
constexpr float kEPS = 1e-5f;

// ---------------- scratch (device globals: allocation-free) ----------------
__device__ float g_q[kNT * kD];
__device__ float g_k[kNT * kD];
__device__ float g_v[kNT * kD];
__device__ float g_proj[kNT * kD];
__device__ float g_x1[kNT * kD];
__device__ float g_y[kNT * kD];
__device__ int   g_cnt[kE];
__device__ int   g_list[kE * kNT];

// bf16 hi/lo planes (activations)
__device__ __nv_bfloat16 g_xb_h[kNT * kD],  g_xb_l[kNT * kD];
__device__ __nv_bfloat16 g_ab_h[kNT * kD],  g_ab_l[kNT * kD];     // attn out
__device__ __nv_bfloat16 g_x1b_h[kNT * kD], g_x1b_l[kNT * kD];
__device__ __nv_bfloat16 g_hb_h[(size_t)kNT * kFF], g_hb_l[(size_t)kNT * kFF];

// bf16 hi/lo planes (transposed weights, [N][K] K-major)
__device__ __nv_bfloat16 g_w4t_h[4 * kD * kD], g_w4t_l[4 * kD * kD];   // Wq,Wk,Wv,Wo
__device__ __nv_bfloat16 g_w1t_h[(size_t)kE * kFF * kD], g_w1t_l[(size_t)kE * kFF * kD];
__device__ __nv_bfloat16 g_w2t_h[(size_t)kE * kFF * kD], g_w2t_l[(size_t)kE * kFF * kD];

// ==================== PTX helpers (base sm_103 features only) ====================
__device__ __forceinline__ uint32_t smem_u32(const void* p) {
    uint32_t a;
    asm("{ .reg .u64 t; cvta.to.shared.u64 t, %1; cvt.u32.u64 %0, t; }" : "=r"(a) : "l"(p));
    return a;
}

__device__ __forceinline__ void cp_async16(uint32_t s, const void* g, int sz) {
    asm volatile("cp.async.cg.shared.global [%0], [%1], 16, %2;"
                 :: "r"(s), "l"(g), "r"(sz) : "memory");
}
#define CP_COMMIT()  asm volatile("cp.async.commit_group;" ::: "memory")
#define CP_WAIT(n)   asm volatile("cp.async.wait_group %0;" :: "n"(n) : "memory")

__device__ __forceinline__ void ldsm_x4(uint32_t& r0, uint32_t& r1, uint32_t& r2,
                                        uint32_t& r3, uint32_t addr) {
    asm volatile("ldmatrix.sync.aligned.m8n8.x4.shared.b16 {%0,%1,%2,%3}, [%4];"
                 : "=r"(r0), "=r"(r1), "=r"(r2), "=r"(r3) : "r"(addr));
}

__device__ __forceinline__ void mma16816(float* d, const uint32_t* a,
                                         uint32_t b0, uint32_t b1) {
    asm volatile("mma.sync.aligned.m16n8k16.row.col.f32.bf16.bf16.f32 "
                 "{%0,%1,%2,%3}, {%4,%5,%6,%7}, {%8,%9}, {%0,%1,%2,%3};"
                 : "+f"(d[0]), "+f"(d[1]), "+f"(d[2]), "+f"(d[3])
                 : "r"(a[0]), "r"(a[1]), "r"(a[2]), "r"(a[3]), "r"(b0), "r"(b1));
}

// ==================== mma.sync split-bf16 GEMM ====================
// D[m][n] = sum_k A[m][k]*B[n][k];  A,B as bf16 hi/lo planes, K-major.
// Block 128x128, K-chunk 32, 2-stage cp.async pipeline, 8 warps (4Mx2N), warp 32x64.
constexpr int kRowB   = 80;                    // padded row bytes (32 bf16 + 8 pad)
constexpr int kPlaneB = 128 * kRowB;           // 10240
constexpr int kStageB = 4 * kPlaneB;           // Ah Al Bh Bl = 40960
constexpr int GEMM_SMEM = 2 * kStageB;         // 81920

struct GemmPtrs {
    const __nv_bfloat16 *aH0, *aL0, *aH1, *aL1;
    const __nv_bfloat16 *bH0, *bL0, *bH1, *bL1;
    int v0, v1, c8;
};

__device__ __forceinline__ void fill_stage(uint32_t sb, int k0, const GemmPtrs& P)
{
    int o = (threadIdx.x >> 2) * kRowB + (threadIdx.x & 3) * 16;
    int g = k0 + P.c8;
    cp_async16(sb + o,                       P.aH0 + g, P.v0 ? 16 : 0);
    cp_async16(sb + o + 64 * kRowB,          P.aH1 + g, P.v1 ? 16 : 0);
    cp_async16(sb + kPlaneB + o,             P.aL0 + g, P.v0 ? 16 : 0);
    cp_async16(sb + kPlaneB + o + 64*kRowB,  P.aL1 + g, P.v1 ? 16 : 0);
    cp_async16(sb + 2*kPlaneB + o,           P.bH0 + g, 16);
    cp_async16(sb + 2*kPlaneB + o + 64*kRowB,P.bH1 + g, 16);
    cp_async16(sb + 3*kPlaneB + o,           P.bL0 + g, 16);
    cp_async16(sb + 3*kPlaneB + o + 64*kRowB,P.bL1 + g, 16);
}

// mode 0: C = acc + bias (fp32);  mode 1: relu(acc+bias) -> Chi/Clo bf16 planes
__device__ __forceinline__ void gemm_tc(
    const __nv_bfloat16* __restrict__ Ah, const __nv_bfloat16* __restrict__ Al,
    const __nv_bfloat16* __restrict__ Bh, const __nv_bfloat16* __restrict__ Bl,
    const float* __restrict__ bias, int K, int count, const int* __restrict__ list,
    int mode, float* __restrict__ C,
    __nv_bfloat16* __restrict__ Chi, __nv_bfloat16* __restrict__ Clo, int ldc)
{
    extern __shared__ char sm[];
    const int tid  = threadIdx.x;
    const int wid  = tid >> 5, lane = tid & 31;
    const int rowBase = blockIdx.y * 128;
    const int colBase = blockIdx.x * 128;
    if (rowBase >= count) return;

    // per-thread cp.async source pointers
    GemmPtrs P;
    {
        int r0 = tid >> 2;
        int gr0 = rowBase + r0, gr1 = rowBase + r0 + 64;
        P.v0 = gr0 < count;
        P.v1 = gr1 < count;
        int rr0 = P.v0 ? (list ? list[gr0] : gr0) : 0;
        int rr1 = P.v1 ? (list ? list[gr1] : gr1) : 0;
        P.aH0 = Ah + (size_t)rr0 * K;  P.aL0 = Al + (size_t)rr0 * K;
        P.aH1 = Ah + (size_t)rr1 * K;  P.aL1 = Al + (size_t)rr1 * K;
        P.bH0 = Bh + (size_t)(colBase + r0) * K;
        P.bH1 = Bh + (size_t)(colBase + r0 + 64) * K;
        P.bL0 = Bl + (size_t)(colBase + r0) * K;
        P.bL1 = Bl + (size_t)(colBase + r0 + 64) * K;
        P.c8  = (tid & 3) * 8;
    }
    const uint32_t smb = smem_u32(sm);

    const int wM = (wid & 3) * 32;
    const int wN = (wid >> 2) * 64;

    float acc[2][8][4];
    #pragma unroll
    for (int i = 0; i < 2; i++)
        #pragma unroll
        for (int j = 0; j < 8; j++)
            #pragma unroll
            for (int d = 0; d < 4; d++) acc[i][j][d] = 0.f;

    const int nc = K / 32;
    fill_stage(smb, 0, P);
    CP_COMMIT();

    // ldmatrix base offsets (relative to stage base)
    const int aRowSel = lane & 15, aColSel = (lane >> 4) * 16;
    const int bRowSel = (lane & 7) + ((lane >> 4) & 1) * 8;
    const int bColSel = ((lane >> 3) & 1) * 16;

    for (int c = 0; c < nc; c++) {
        if (c + 1 < nc) {
            fill_stage(smb + ((c + 1) & 1) * kStageB, (c + 1) * 32, P);
            CP_COMMIT();
            CP_WAIT(1);
        } else {
            CP_WAIT(0);
        }
        __syncthreads();

        uint32_t st = smb + (c & 1) * kStageB;
        #pragma unroll
        for (int s = 0; s < 2; s++) {
            const int kb = s * 32;   // 16 bf16 = 32 bytes
            uint32_t ah[2][4], al[2][4];
            #pragma unroll
            for (int mi = 0; mi < 2; mi++) {
                uint32_t ra = st + (wM + mi * 16 + aRowSel) * kRowB + kb + aColSel;
                ldsm_x4(ah[mi][0], ah[mi][1], ah[mi][2], ah[mi][3], ra);
                ldsm_x4(al[mi][0], al[mi][1], al[mi][2], al[mi][3], ra + kPlaneB);
            }
            #pragma unroll
            for (int njp = 0; njp < 4; njp++) {
                uint32_t rb = st + 2 * kPlaneB
                            + (wN + njp * 16 + bRowSel) * kRowB + kb + bColSel;
                uint32_t bh[4], bl[4];
                ldsm_x4(bh[0], bh[1], bh[2], bh[3], rb);
                ldsm_x4(bl[0], bl[1], bl[2], bl[3], rb + kPlaneB);
                #pragma unroll
                for (int mi = 0; mi < 2; mi++) {
                    #pragma unroll
                    for (int half = 0; half < 2; half++) {
                        float* d = acc[mi][njp * 2 + half];
                        mma16816(d, ah[mi], bh[half * 2], bh[half * 2 + 1]);
                        mma16816(d, ah[mi], bl[half * 2], bl[half * 2 + 1]);
                        mma16816(d, al[mi], bh[half * 2], bh[half * 2 + 1]);
                    }
                }
            }
        }
        __syncthreads();
    }

    // epilogue: thread owns D(m,n): m = wM+mi*16+lane/4 (+8 for d2,d3),
    //                               n = wN+nj*8+(lane%4)*2 (+1)
    #pragma unroll
    for (int mi = 0; mi < 2; mi++) {
        #pragma unroll
        for (int dd = 0; dd < 2; dd++) {
            int lrow = rowBase + wM + mi * 16 + (lane >> 2) + dd * 8;
            if (lrow >= count) continue;
            int orow = list ? list[lrow] : lrow;
            #pragma unroll
            for (int nj = 0; nj < 8; nj++) {
                int n = colBase + wN + nj * 8 + (lane & 3) * 2;
                float v0 = acc[mi][nj][dd * 2 + 0] + bias[n];
                float v1 = acc[mi][nj][dd * 2 + 1] + bias[n + 1];
                if (mode == 0) {
                    C[(size_t)orow * ldc + n]     = v0;
                    C[(size_t)orow * ldc + n + 1] = v1;
                } else {
                    v0 = fmaxf(v0, 0.f); v1 = fmaxf(v1, 0.f);
                    size_t o = (size_t)orow * ldc + n;
                    __nv_bfloat16 h0 = __float2bfloat16_rn(v0);
                    __nv_bfloat16 h1 = __float2bfloat16_rn(v1);
                    Chi[o]     = h0;
                    Chi[o + 1] = h1;
                    Clo[o]     = __float2bfloat16_rn(v0 - __bfloat162float(h0));
                    Clo[o + 1] = __float2bfloat16_rn(v1 - __bfloat162float(h1));
                }
            }
        }
    }
}

// ---------------- GEMM wrappers ----------------
__global__ void __launch_bounds__(256) qkv_tc(const float* bq, const float* bk, const float* bv)
{
    int z = blockIdx.z;
    const __nv_bfloat16* bh = g_w4t_h + (size_t)z * kD * kD;
    const __nv_bfloat16* bl = g_w4t_l + (size_t)z * kD * kD;
    float* C = (z == 0) ? g_q : (z == 1) ? g_k : g_v;
    const float* bias = (z == 0) ? bq : (z == 1) ? bk : bv;
    gemm_tc(g_xb_h, g_xb_l, bh, bl, bias, kD, kNT, nullptr, 0, C, nullptr, nullptr, kD);
}

__global__ void __launch_bounds__(256) proj_tc(const float* bo)
{
    gemm_tc(g_ab_h, g_ab_l, g_w4t_h + (size_t)3 * kD * kD, g_w4t_l + (size_t)3 * kD * kD,
            bo, kD, kNT, nullptr, 0, g_proj, nullptr, nullptr, kD);
}

__global__ void __launch_bounds__(256) moe1_tc(const float* b1e)
{
    int e = blockIdx.z;
    int cnt = g_cnt[e];
    gemm_tc(g_x1b_h, g_x1b_l,
            g_w1t_h + (size_t)e * kFF * kD, g_w1t_l + (size_t)e * kFF * kD,
            b1e + (size_t)e * kFF, kD, cnt, g_list + e * kNT,
            1, nullptr, g_hb_h, g_hb_l, kFF);
}

__global__ void __launch_bounds__(256) moe2_tc(const float* b2e)
{
    int e = blockIdx.z;
    int cnt = g_cnt[e];
    gemm_tc(g_hb_h, g_hb_l,
            g_w2t_h + (size_t)e * kFF * kD, g_w2t_l + (size_t)e * kFF * kD,
            b2e + (size_t)e * kD, kFF, cnt, g_list + e * kNT,
            0, g_y, nullptr, nullptr, kD);
}

// ---------------- conversion kernels ----------------
__global__ void convert_x(const float* __restrict__ x)
{
    int i = blockIdx.x * 256 + threadIdx.x;          // one float4 each
    float4 v = ((const float4*)x)[i];
    size_t o = (size_t)i * 4;
    float a[4] = {v.x, v.y, v.z, v.w};
    #pragma unroll
    for (int j = 0; j < 4; j++) {
        __nv_bfloat16 h = __float2bfloat16_rn(a[j]);
        g_xb_h[o + j] = h;
        g_xb_l[o + j] = __float2bfloat16_rn(a[j] - __bfloat162float(h));
    }
}

__device__ __forceinline__ void transpose_body(
    const float* __restrict__ src, __nv_bfloat16* __restrict__ hi,
    __nv_bfloat16* __restrict__ lo, int K, int N)
{
    __shared__ float tile[32][33];
    int bn = blockIdx.x * 32, bk = blockIdx.y * 32;
    int tx = threadIdx.x, ty = threadIdx.y;
    #pragma unroll
    for (int i = 0; i < 32; i += 8)
        tile[ty + i][tx] = src[(size_t)(bk + ty + i) * N + bn + tx];
    __syncthreads();
    #pragma unroll
    for (int i = 0; i < 32; i += 8) {
        float v = tile[tx][ty + i];
        __nv_bfloat16 h = __float2bfloat16_rn(v);
        size_t o = (size_t)(bn + ty + i) * K + bk + tx;
        hi[o] = h;
        lo[o] = __float2bfloat16_rn(v - __bfloat162float(h));
    }
}

__global__ void transpose_qkvo(const float* Wq, const float* Wk, const float* Wv, const float* Wo)
{
    int z = blockIdx.z;
    const float* src = (z == 0) ? Wq : (z == 1) ? Wk : (z == 2) ? Wv : Wo;
    transpose_body(src, g_w4t_h + (size_t)z * kD * kD, g_w4t_l + (size_t)z * kD * kD, kD, kD);
}

__global__ void transpose_w1(const float* W1e)
{
    int e = blockIdx.z;
    size_t off = (size_t)e * kD * kFF;
    transpose_body(W1e + off, g_w1t_h + off, g_w1t_l + off, kD, kFF);
}

__global__ void transpose_w2(const float* W2e)
{
    int e = blockIdx.z;
    size_t off = (size_t)e * kFF * kD;
    transpose_body(W2e + off, g_w2t_h + off, g_w2t_l + off, kFF, kD);
}

// ---------------- flash attention (causal, fp32 SIMT) ----------------
constexpr int kAttnSmem = (64*68 + 64*68 + 64*64 + 64*64) * 4;   // 67584 B

__global__ void attn_kernel()
{
    extern __shared__ float smf[];
    float* Qs = smf;
    float* Ks = smf + 64*68;
    float* Vs = smf + 2*64*68;
    float* Ps = smf + 2*64*68 + 64*64;

    const int tid = threadIdx.x;
    const int ty = tid >> 4;
    const int tx = tid & 15;
    const int bh = blockIdx.y;
    const int b = bh >> 4;
    const int h = bh & 15;
    const int qt = blockIdx.x;
    const int qbase = qt * 64;

    const float* Qg = g_q + (size_t)b * kT * kD + (size_t)h * kDH;
    const float* Kg = g_k + (size_t)b * kT * kD + (size_t)h * kDH;
    const float* Vg = g_v + (size_t)b * kT * kD + (size_t)h * kDH;

    #pragma unroll
    for (int l = 0; l < 4; l++) {
        int fid = tid + l * 256;
        int r = fid & 63;
        int d4 = fid >> 6;
        float4 v = *(const float4*)(Qg + (size_t)(qbase + r) * kD + d4 * 4);
        Qs[(d4*4+0)*68 + r] = v.x;
        Qs[(d4*4+1)*68 + r] = v.y;
        Qs[(d4*4+2)*68 + r] = v.z;
        Qs[(d4*4+3)*68 + r] = v.w;
    }
    __syncthreads();

    float mrow[4], lrow[4], o[4][4];
    #pragma unroll
    for (int i = 0; i < 4; i++) {
        mrow[i] = -INFINITY; lrow[i] = 0.f;
        #pragma unroll
        for (int j = 0; j < 4; j++) o[i][j] = 0.f;
    }

    for (int kt = 0; kt <= qt; kt++) {
        int kbase = kt * 64;
        #pragma unroll
        for (int l = 0; l < 16; l++) {
            int idx = tid + l * 256;
            int c = idx >> 6, d = idx & 63;
            Ks[d*68 + c] = Kg[(size_t)(kbase + c) * kD + d];
        }
        #pragma unroll
        for (int l = 0; l < 4; l++) {
            int fid = tid + l * 256;
            int c = fid >> 4, d4 = fid & 15;
            *(float4*)&Vs[c*64 + d4*4] =
                *(const float4*)(Vg + (size_t)(kbase + c) * kD + d4 * 4);
        }
        __syncthreads();

        float s[4][4];
        #pragma unroll
        for (int i = 0; i < 4; i++)
            #pragma unroll
            for (int j = 0; j < 4; j++) s[i][j] = 0.f;

        #pragma unroll 8
        for (int d = 0; d < 64; d++) {
            float4 qv = *(const float4*)&Qs[d*68 + ty*4];
            float4 kv = *(const float4*)&Ks[d*68 + tx*4];
            float qa[4] = {qv.x, qv.y, qv.z, qv.w};
            float ka[4] = {kv.x, kv.y, kv.z, kv.w};
            #pragma unroll
            for (int i = 0; i < 4; i++)
                #pragma unroll
                for (int j = 0; j < 4; j++)
                    s[i][j] = fmaf(qa[i], ka[j], s[i][j]);
        }

        const bool diag = (kt == qt);
        #pragma unroll
        for (int i = 0; i < 4; i++) {
            int r = ty*4 + i;
            float sv[4];
            #pragma unroll
            for (int j = 0; j < 4; j++) {
                float val = s[i][j] * 0.125f;
                if (diag && (tx*4 + j) > r) val = -INFINITY;
                sv[j] = val;
            }
            float mp = fmaxf(fmaxf(sv[0], sv[1]), fmaxf(sv[2], sv[3]));
            #pragma unroll
            for (int o2 = 8; o2; o2 >>= 1)
                mp = fmaxf(mp, __shfl_xor_sync(0xffffffffu, mp, o2));
            float mn = fmaxf(mrow[i], mp);
            float corr = __expf(mrow[i] - mn);
            float ps = 0.f;
            #pragma unroll
            for (int j = 0; j < 4; j++) {
                float p = __expf(sv[j] - mn);
                Ps[r*64 + tx*4 + j] = p;
                ps += p;
            }
            #pragma unroll
            for (int o2 = 8; o2; o2 >>= 1)
                ps += __shfl_xor_sync(0xffffffffu, ps, o2);
            lrow[i] = lrow[i] * corr + ps;
            mrow[i] = mn;
            #pragma unroll
            for (int j = 0; j < 4; j++) o[i][j] *= corr;
        }
        __syncthreads();

        #pragma unroll 4
        for (int c = 0; c < 64; c++) {
            float4 vv = *(const float4*)&Vs[c*64 + tx*4];
            float va[4] = {vv.x, vv.y, vv.z, vv.w};
            float pa[4];
            #pragma unroll
            for (int i = 0; i < 4; i++) pa[i] = Ps[(ty*4+i)*64 + c];
            #pragma unroll
            for (int i = 0; i < 4; i++)
                #pragma unroll
                for (int j = 0; j < 4; j++)
                    o[i][j] = fmaf(pa[i], va[j], o[i][j]);
        }
        __syncthreads();
    }

    // epilogue: write bf16 hi/lo planes directly
    #pragma unroll
    for (int i = 0; i < 4; i++) {
        float inv = 1.f / lrow[i];
        size_t base = (size_t)(b * kT + qbase + ty*4 + i) * kD + (size_t)h * kDH + tx*4;
        #pragma unroll
        for (int j = 0; j < 4; j++) {
            float v = o[i][j] * inv;
            __nv_bfloat16 hh = __float2bfloat16_rn(v);
            g_ab_h[base + j] = hh;
            g_ab_l[base + j] = __float2bfloat16_rn(v - __bfloat162float(hh));
        }
    }
}

// ---------------- add + layernorm ----------------
__device__ __forceinline__ float block_sum_256(float v, float* red)
{
    int tid = threadIdx.x;
    #pragma unroll
    for (int o = 16; o; o >>= 1) v += __shfl_xor_sync(0xffffffffu, v, o);
    if ((tid & 31) == 0) red[tid >> 5] = v;
    __syncthreads();
    if (tid < 8) {
        float x = red[tid];
        #pragma unroll
        for (int o = 4; o; o >>= 1) x += __shfl_xor_sync(0xffu, x, o);
        if (tid == 0) red[0] = x;
    }
    __syncthreads();
    float r = red[0];
    __syncthreads();
    return r;
}

__device__ __forceinline__ void add_ln_body(
    const float* __restrict__ A, const float* __restrict__ Bb,
    const float* __restrict__ gw, const float* __restrict__ bw,
    float* __restrict__ out, __nv_bfloat16* __restrict__ oh,
    __nv_bfloat16* __restrict__ ol)
{
    __shared__ float red[8];
    int t = blockIdx.x, tid = threadIdx.x;
    float4 av = ((const float4*)(A  + (size_t)t * kD))[tid];
    float4 bv = ((const float4*)(Bb + (size_t)t * kD))[tid];
    float vx = av.x + bv.x, vy = av.y + bv.y, vz = av.z + bv.z, vw = av.w + bv.w;
    float ssum = block_sum_256(vx + vy + vz + vw, red);
    float mu = ssum * (1.0f / kD);
    float dx = vx - mu, dy = vy - mu, dz = vz - mu, dw = vw - mu;
    float sq = block_sum_256(dx*dx + dy*dy + dz*dz + dw*dw, red);
    float rstd = rsqrtf(sq * (1.0f / kD) + kEPS);
    float4 gv = ((const float4*)gw)[tid];
    float4 be = ((const float4*)bw)[tid];
    float ovv[4] = {dx*rstd*gv.x + be.x, dy*rstd*gv.y + be.y,
                    dz*rstd*gv.z + be.z, dw*rstd*gv.w + be.w};
    ((float4*)(out + (size_t)t * kD))[tid] = make_float4(ovv[0], ovv[1], ovv[2], ovv[3]);
    if (oh) {
        size_t o = (size_t)t * kD + tid * 4;
        #pragma unroll
        for (int j = 0; j < 4; j++) {
            __nv_bfloat16 h = __float2bfloat16_rn(ovv[j]);
            oh[o + j] = h;
            ol[o + j] = __float2bfloat16_rn(ovv[j] - __bfloat162float(h));
        }
    }
}

__global__ void ln1_kernel(const float* __restrict__ x,
                           const float* __restrict__ g, const float* __restrict__ b)
{
    add_ln_body(x, g_proj, g, b, g_x1, g_x1b_h, g_x1b_l);
}

__global__ void ln2_kernel(const float* __restrict__ g, const float* __restrict__ b,
                           float* __restrict__ out)
{
    add_ln_body(g_x1, g_y, g, b, out, nullptr, nullptr);
}

// ---------------- MoE gate (top-1 argmax) ----------------
__global__ void zero_cnt()
{
    if (threadIdx.x < kE) g_cnt[threadIdx.x] = 0;
}

__global__ void gate_kernel(const float* __restrict__ Wg, const float* __restrict__ bg)
{
    int t = blockIdx.x, tid = threadIdx.x;
    float a0 = 0.f, a1 = 0.f, a2 = 0.f, a3 = 0.f;
    const float* xr = g_x1 + (size_t)t * kD;
    for (int d = tid; d < kD; d += 128) {
        float xv = xr[d];
        float4 w = ((const float4*)Wg)[d];
        a0 = fmaf(xv, w.x, a0);
        a1 = fmaf(xv, w.y, a1);
        a2 = fmaf(xv, w.z, a2);
        a3 = fmaf(xv, w.w, a3);
    }
    __shared__ float rsm[4][128];
    rsm[0][tid] = a0; rsm[1][tid] = a1; rsm[2][tid] = a2; rsm[3][tid] = a3;
    __syncthreads();
    for (int s = 64; s > 0; s >>= 1) {
        if (tid < s) {
            #pragma unroll
            for (int e = 0; e < 4; e++) rsm[e][tid] += rsm[e][tid + s];
        }
        __syncthreads();
    }
    if (tid == 0) {
        float sc[4];
        #pragma unroll
        for (int e = 0; e < 4; e++) sc[e] = rsm[e][0] + bg[e];
        int best = 0; float bvv = sc[0];
        #pragma unroll
        for (int e = 1; e < 4; e++) {
            if (sc[e] > bvv) { bvv = sc[e]; best = e; }
        }
        int pos = atomicAdd(&g_cnt[best], 1);
        g_list[best * kNT + pos] = t;
    }
}

// ---------------- launch ----------------
extern "C" void kernel_launch(void* const* d_in, const int* in_sizes, int n_in,
                              void* d_out, int out_size)
{
    const float* x    = (const float*)d_in[0];
    const float* Wq   = (const float*)d_in[2];
    const float* bq   = (const float*)d_in[3];
    const float* Wk   = (const float*)d_in[4];
    const float* bk   = (const float*)d_in[5];
    const float* Wv   = (const float*)d_in[6];
    const float* bv   = (const float*)d_in[7];
    const float* Wo   = (const float*)d_in[8];
    const float* bo   = (const float*)d_in[9];
    const float* ln1g = (const float*)d_in[10];
    const float* ln1b = (const float*)d_in[11];
    const float* Wg   = (const float*)d_in[12];
    const float* bg   = (const float*)d_in[13];
    const float* W1e  = (const float*)d_in[14];
    const float* b1e  = (const float*)d_in[15];
    const float* W2e  = (const float*)d_in[16];
    const float* b2e  = (const float*)d_in[17];
    const float* ln2g = (const float*)d_in[18];
    const float* ln2b = (const float*)d_in[19];
    float* out = (float*)d_out;

    cudaFuncSetAttribute(attn_kernel, cudaFuncAttributeMaxDynamicSharedMemorySize, kAttnSmem);
    cudaFuncSetAttribute(qkv_tc,  cudaFuncAttributeMaxDynamicSharedMemorySize, GEMM_SMEM);
    cudaFuncSetAttribute(proj_tc, cudaFuncAttributeMaxDynamicSharedMemorySize, GEMM_SMEM);
    cudaFuncSetAttribute(moe1_tc, cudaFuncAttributeMaxDynamicSharedMemorySize, GEMM_SMEM);
    cudaFuncSetAttribute(moe2_tc, cudaFuncAttributeMaxDynamicSharedMemorySize, GEMM_SMEM);

    // weight/activation prep
    convert_x<<<kNT * kD / 4 / 256, 256>>>(x);
    transpose_qkvo<<<dim3(kD/32, kD/32, 4), dim3(32, 8)>>>(Wq, Wk, Wv, Wo);
    transpose_w1<<<dim3(kFF/32, kD/32, kE), dim3(32, 8)>>>(W1e);
    transpose_w2<<<dim3(kD/32, kFF/32, kE), dim3(32, 8)>>>(W2e);

    // attention path
    qkv_tc<<<dim3(kD/128, kNT/128, 3), 256, GEMM_SMEM>>>(bq, bk, bv);
    attn_kernel<<<dim3(kT/64, kB*kH), 256, kAttnSmem>>>();
    proj_tc<<<dim3(kD/128, kNT/128), 256, GEMM_SMEM>>>(bo);
    ln1_kernel<<<kNT, 256>>>(x, ln1g, ln1b);

    // MoE path
    zero_cnt<<<1, 32>>>();
    gate_kernel<<<kNT, 128>>>(Wg, bg);
    moe1_tc<<<dim3(kFF/128, kNT/128, kE), 256, GEMM_SMEM>>>(b1e);
    moe2_tc<<<dim3(kD/128, kNT/128, kE), 256, GEMM_SMEM>>>(b2e);
    ln2_kernel<<<kNT, 256>>>(ln2g, ln2b, out);
}

// round 4
// speedup vs baseline: 2.1820x; 1.3355x over previous
#include <cuda_runtime.h>
#include <cuda_bf16.h>
#include <math.h>
#include <stdint.h>

// ---------------- problem constants ----------------
constexpr int kB  = 2;
constexpr int kT  = 2048;
constexpr int kD  = 1024;
constexpr int kH  = 16;
constexpr int kDH = 64;
constexpr int kFF = 4096;
constexpr int kE  = 4;
constexpr int kNT = kB * kT;           // 4096 tokens
constexpr float kEPS = 1e-5f;

// ---------------- scratch (device globals: allocation-free) ----------------
__device__ float g_proj[kNT * kD];
__device__ float g_x1[kNT * kD];
__device__ float g_y[kNT * kD];
__device__ int   g_cnt[kE];
__device__ int   g_list[kE * kNT];

// bf16 hi/lo planes (activations)
__device__ __nv_bfloat16 g_xb_h[kNT * kD],  g_xb_l[kNT * kD];
__device__ __nv_bfloat16 g_qb_h[kNT * kD],  g_qb_l[kNT * kD];
__device__ __nv_bfloat16 g_kb_h[kNT * kD],  g_kb_l[kNT * kD];
__device__ __nv_bfloat16 g_vb_h[kNT * kD],  g_vb_l[kNT * kD];
__device__ __nv_bfloat16 g_ab_h[kNT * kD],  g_ab_l[kNT * kD];     // attn out
__device__ __nv_bfloat16 g_x1b_h[kNT * kD], g_x1b_l[kNT * kD];
__device__ __nv_bfloat16 g_hb_h[(size_t)kNT * kFF], g_hb_l[(size_t)kNT * kFF];

// bf16 hi/lo planes (transposed weights, [N][K] K-major)
__device__ __nv_bfloat16 g_w4t_h[4 * kD * kD], g_w4t_l[4 * kD * kD];   // Wq,Wk,Wv,Wo
__device__ __nv_bfloat16 g_w1t_h[(size_t)kE * kFF * kD], g_w1t_l[(size_t)kE * kFF * kD];
__device__ __nv_bfloat16 g_w2t_h[(size_t)kE * kFF * kD], g_w2t_l[(size_t)kE * kFF * kD];

// ==================== PTX helpers (base sm_103 features only) ====================
__device__ __forceinline__ uint32_t smem_u32(const void* p) {
    uint32_t a;
    asm("{ .reg .u64 t; cvta.to.shared.u64 t, %1; cvt.u32.u64 %0, t; }" : "=r"(a) : "l"(p));
    return a;
}

__device__ __forceinline__ void cp_async16(uint32_t s, const void* g, int sz) {
    asm volatile("cp.async.cg.shared.global [%0], [%1], 16, %2;"
                 :: "r"(s), "l"(g), "r"(sz) : "memory");
}
#define CP_COMMIT()  asm volatile("cp.async.commit_group;" ::: "memory")
#define CP_WAIT(n)   asm volatile("cp.async.wait_group %0;" :: "n"(n) : "memory")

__device__ __forceinline__ void ldsm_x4(uint32_t& r0, uint32_t& r1, uint32_t& r2,
                                        uint32_t& r3, uint32_t addr) {
    asm volatile("ldmatrix.sync.aligned.m8n8.x4.shared.b16 {%0,%1,%2,%3}, [%4];"
                 : "=r"(r0), "=r"(r1), "=r"(r2), "=r"(r3) : "r"(addr));
}
__device__ __forceinline__ void ldsm_x4_t(uint32_t& r0, uint32_t& r1, uint32_t& r2,
                                          uint32_t& r3, uint32_t addr) {
    asm volatile("ldmatrix.sync.aligned.m8n8.x4.trans.shared.b16 {%0,%1,%2,%3}, [%4];"
                 : "=r"(r0), "=r"(r1), "=r"(r2), "=r"(r3) : "r"(addr));
}

__device__ __forceinline__ void mma16816(float* d, const uint32_t* a,
                                         uint32_t b0, uint32_t b1) {
    asm volatile("mma.sync.aligned.m16n8k16.row.col.f32.bf16.bf16.f32 "
                 "{%0,%1,%2,%3}, {%4,%5,%6,%7}, {%8,%9}, {%0,%1,%2,%3};"
                 : "+f"(d[0]), "+f"(d[1]), "+f"(d[2]), "+f"(d[3])
                 : "r"(a[0]), "r"(a[1]), "r"(a[2]), "r"(a[3]), "r"(b0), "r"(b1));
}

// split (f0,f1) into packed bf16 hi and lo planes
__device__ __forceinline__ void split2(float f0, float f1, uint32_t& h, uint32_t& l) {
    __nv_bfloat162 hv = __floats2bfloat162_rn(f0, f1);
    float r0 = f0 - __bfloat162float(hv.x);
    float r1 = f1 - __bfloat162float(hv.y);
    __nv_bfloat162 lv = __floats2bfloat162_rn(r0, r1);
    h = *reinterpret_cast<uint32_t*>(&hv);
    l = *reinterpret_cast<uint32_t*>(&lv);
}

// ==================== mma.sync split-bf16 GEMM ====================
constexpr int kRowB   = 80;                    // padded row bytes (32 bf16 + 8 pad)
constexpr int kPlaneB = 128 * kRowB;           // 10240
constexpr int kStageB = 4 * kPlaneB;           // Ah Al Bh Bl = 40960
constexpr int GEMM_SMEM = 2 * kStageB;         // 81920

struct GemmPtrs {
    const __nv_bfloat16 *aH0, *aL0, *aH1, *aL1;
    const __nv_bfloat16 *bH0, *bL0, *bH1, *bL1;
    int v0, v1, c8;
};

__device__ __forceinline__ void fill_stage(uint32_t sb, int k0, const GemmPtrs& P)
{
    int o = (threadIdx.x >> 2) * kRowB + (threadIdx.x & 3) * 16;
    int g = k0 + P.c8;
    cp_async16(sb + o,                       P.aH0 + g, P.v0 ? 16 : 0);
    cp_async16(sb + o + 64 * kRowB,          P.aH1 + g, P.v1 ? 16 : 0);
    cp_async16(sb + kPlaneB + o,             P.aL0 + g, P.v0 ? 16 : 0);
    cp_async16(sb + kPlaneB + o + 64*kRowB,  P.aL1 + g, P.v1 ? 16 : 0);
    cp_async16(sb + 2*kPlaneB + o,           P.bH0 + g, 16);
    cp_async16(sb + 2*kPlaneB + o + 64*kRowB,P.bH1 + g, 16);
    cp_async16(sb + 3*kPlaneB + o,           P.bL0 + g, 16);
    cp_async16(sb + 3*kPlaneB + o + 64*kRowB,P.bL1 + g, 16);
}

// mode 0: C = acc + bias (fp32)
// mode 1: relu(acc+bias) -> Chi/Clo bf16 planes
// mode 2: (acc+bias)*scale -> Chi/Clo bf16 planes
__device__ __forceinline__ void gemm_tc(
    const __nv_bfloat16* __restrict__ Ah, const __nv_bfloat16* __restrict__ Al,
    const __nv_bfloat16* __restrict__ Bh, const __nv_bfloat16* __restrict__ Bl,
    const float* __restrict__ bias, int K, int count, const int* __restrict__ list,
    int mode, float* __restrict__ C,
    __nv_bfloat16* __restrict__ Chi, __nv_bfloat16* __restrict__ Clo, int ldc,
    float scale)
{
    extern __shared__ char sm[];
    const int tid  = threadIdx.x;
    const int wid  = tid >> 5, lane = tid & 31;
    const int rowBase = blockIdx.y * 128;
    const int colBase = blockIdx.x * 128;
    if (rowBase >= count) return;

    GemmPtrs P;
    {
        int r0 = tid >> 2;
        int gr0 = rowBase + r0, gr1 = rowBase + r0 + 64;
        P.v0 = gr0 < count;
        P.v1 = gr1 < count;
        int rr0 = P.v0 ? (list ? list[gr0] : gr0) : 0;
        int rr1 = P.v1 ? (list ? list[gr1] : gr1) : 0;
        P.aH0 = Ah + (size_t)rr0 * K;  P.aL0 = Al + (size_t)rr0 * K;
        P.aH1 = Ah + (size_t)rr1 * K;  P.aL1 = Al + (size_t)rr1 * K;
        P.bH0 = Bh + (size_t)(colBase + r0) * K;
        P.bH1 = Bh + (size_t)(colBase + r0 + 64) * K;
        P.bL0 = Bl + (size_t)(colBase + r0) * K;
        P.bL1 = Bl + (size_t)(colBase + r0 + 64) * K;
        P.c8  = (tid & 3) * 8;
    }
    const uint32_t smb = smem_u32(sm);

    const int wM = (wid & 3) * 32;
    const int wN = (wid >> 2) * 64;

    float acc[2][8][4];
    #pragma unroll
    for (int i = 0; i < 2; i++)
        #pragma unroll
        for (int j = 0; j < 8; j++)
            #pragma unroll
            for (int d = 0; d < 4; d++) acc[i][j][d] = 0.f;

    const int nc = K / 32;
    fill_stage(smb, 0, P);
    CP_COMMIT();

    const int aRowSel = lane & 15, aColSel = (lane >> 4) * 16;
    const int bRowSel = (lane & 7) + ((lane >> 4) & 1) * 8;
    const int bColSel = ((lane >> 3) & 1) * 16;

    for (int c = 0; c < nc; c++) {
        if (c + 1 < nc) {
            fill_stage(smb + ((c + 1) & 1) * kStageB, (c + 1) * 32, P);
            CP_COMMIT();
            CP_WAIT(1);
        } else {
            CP_WAIT(0);
        }
        __syncthreads();

        uint32_t st = smb + (c & 1) * kStageB;
        #pragma unroll
        for (int s = 0; s < 2; s++) {
            const int kb = s * 32;
            uint32_t ah[2][4], al[2][4];
            #pragma unroll
            for (int mi = 0; mi < 2; mi++) {
                uint32_t ra = st + (wM + mi * 16 + aRowSel) * kRowB + kb + aColSel;
                ldsm_x4(ah[mi][0], ah[mi][1], ah[mi][2], ah[mi][3], ra);
                ldsm_x4(al[mi][0], al[mi][1], al[mi][2], al[mi][3], ra + kPlaneB);
            }
            #pragma unroll
            for (int njp = 0; njp < 4; njp++) {
                uint32_t rb = st + 2 * kPlaneB
                            + (wN + njp * 16 + bRowSel) * kRowB + kb + bColSel;
                uint32_t bh[4], bl[4];
                ldsm_x4(bh[0], bh[1], bh[2], bh[3], rb);
                ldsm_x4(bl[0], bl[1], bl[2], bl[3], rb + kPlaneB);
                #pragma unroll
                for (int mi = 0; mi < 2; mi++) {
                    #pragma unroll
                    for (int half = 0; half < 2; half++) {
                        float* d = acc[mi][njp * 2 + half];
                        mma16816(d, ah[mi], bh[half * 2], bh[half * 2 + 1]);
                        mma16816(d, ah[mi], bl[half * 2], bl[half * 2 + 1]);
                        mma16816(d, al[mi], bh[half * 2], bh[half * 2 + 1]);
                    }
                }
            }
        }
        __syncthreads();
    }

    #pragma unroll
    for (int mi = 0; mi < 2; mi++) {
        #pragma unroll
        for (int dd = 0; dd < 2; dd++) {
            int lrow = rowBase + wM + mi * 16 + (lane >> 2) + dd * 8;
            if (lrow >= count) continue;
            int orow = list ? list[lrow] : lrow;
            #pragma unroll
            for (int nj = 0; nj < 8; nj++) {
                int n = colBase + wN + nj * 8 + (lane & 3) * 2;
                float v0 = acc[mi][nj][dd * 2 + 0] + bias[n];
                float v1 = acc[mi][nj][dd * 2 + 1] + bias[n + 1];
                if (mode == 0) {
                    C[(size_t)orow * ldc + n]     = v0;
                    C[(size_t)orow * ldc + n + 1] = v1;
                } else {
                    if (mode == 1) { v0 = fmaxf(v0, 0.f); v1 = fmaxf(v1, 0.f); }
                    else           { v0 *= scale; v1 *= scale; }
                    size_t o = (size_t)orow * ldc + n;
                    uint32_t hh, ll;
                    split2(v0, v1, hh, ll);
                    *reinterpret_cast<uint32_t*>(Chi + o) = hh;
                    *reinterpret_cast<uint32_t*>(Clo + o) = ll;
                }
            }
        }
    }
}

// ---------------- GEMM wrappers ----------------
__global__ void __launch_bounds__(256) qkv_tc(const float* bq, const float* bk, const float* bv)
{
    int z = blockIdx.z;
    const __nv_bfloat16* bh = g_w4t_h + (size_t)z * kD * kD;
    const __nv_bfloat16* bl = g_w4t_l + (size_t)z * kD * kD;
    __nv_bfloat16* ch = (z == 0) ? g_qb_h : (z == 1) ? g_kb_h : g_vb_h;
    __nv_bfloat16* cl = (z == 0) ? g_qb_l : (z == 1) ? g_kb_l : g_vb_l;
    const float* bias = (z == 0) ? bq : (z == 1) ? bk : bv;
    float scale = (z == 0) ? 0.125f : 1.0f;
    gemm_tc(g_xb_h, g_xb_l, bh, bl, bias, kD, kNT, nullptr, 2, nullptr, ch, cl, kD, scale);
}

__global__ void __launch_bounds__(256) proj_tc(const float* bo)
{
    gemm_tc(g_ab_h, g_ab_l, g_w4t_h + (size_t)3 * kD * kD, g_w4t_l + (size_t)3 * kD * kD,
            bo, kD, kNT, nullptr, 0, g_proj, nullptr, nullptr, kD, 1.f);
}

__global__ void __launch_bounds__(256) moe1_tc(const float* b1e)
{
    int e = blockIdx.z;
    int cnt = g_cnt[e];
    gemm_tc(g_x1b_h, g_x1b_l,
            g_w1t_h + (size_t)e * kFF * kD, g_w1t_l + (size_t)e * kFF * kD,
            b1e + (size_t)e * kFF, kD, cnt, g_list + e * kNT,
            1, nullptr, g_hb_h, g_hb_l, kFF, 1.f);
}

__global__ void __launch_bounds__(256) moe2_tc(const float* b2e)
{
    int e = blockIdx.z;
    int cnt = g_cnt[e];
    gemm_tc(g_hb_h, g_hb_l,
            g_w2t_h + (size_t)e * kFF * kD, g_w2t_l + (size_t)e * kFF * kD,
            b2e + (size_t)e * kD, kFF, cnt, g_list + e * kNT,
            0, g_y, nullptr, nullptr, kD, 1.f);
}

// ==================== HMMA flash attention (causal, split bf16) ====================
// Q pre-scaled by 0.125 in qkv epilogue. q-tile 128 (8 warps x m16), kv-tile 64.
constexpr int kARS    = 144;                   // padded row bytes (64 bf16 + 8 pad)
constexpr int kAPlane = 64 * kARS;             // 9216
constexpr int kAStage = 4 * kAPlane;           // Kh Kl Vh Vl = 36864
constexpr int ATTN_SMEM = 2 * kAStage;         // 73728

__device__ __forceinline__ void fill_kv(uint32_t dst, int b, int h, int kbase)
{
    const __nv_bfloat16* srcs[4] = {g_kb_h, g_kb_l, g_vb_h, g_vb_l};
    #pragma unroll
    for (int i = 0; i < 8; i++) {
        int lin = threadIdx.x + 256 * i;
        int ch = lin & 7, row = (lin >> 3) & 63, pl = lin >> 9;
        const __nv_bfloat16* src = srcs[pl]
            + ((size_t)(b * kT + kbase + row) * kD + h * 64 + ch * 8);
        cp_async16(dst + pl * kAPlane + row * kARS + ch * 16, src, 16);
    }
}

__global__ void __launch_bounds__(256) attn_tc()
{
    extern __shared__ char sa[];
    const uint32_t smb = smem_u32(sa);
    const int tid = threadIdx.x, wid = tid >> 5, lane = tid & 31;
    const int qt = blockIdx.x;                 // 0..15
    const int bh = blockIdx.y;
    const int b = bh >> 4, h = bh & 15;
    const int qb = qt * 128;
    const int wr0 = qb + wid * 16;             // warp's first q row

    // ---- load Q tile (128 x 64, hi/lo) into stage1 region ----
    #pragma unroll
    for (int i = 0; i < 8; i++) {
        int lin = tid + 256 * i;
        int ch = lin & 7, row = (lin >> 3) & 127, pl = lin >> 10;
        const __nv_bfloat16* src = (pl ? g_qb_l : g_qb_h)
            + ((size_t)(b * kT + qb + row) * kD + h * 64 + ch * 8);
        cp_async16(smb + kAStage + pl * (128 * kARS) + row * kARS + ch * 16, src, 16);
    }
    CP_COMMIT();
    fill_kv(smb, b, h, 0);
    CP_COMMIT();
    CP_WAIT(0);
    __syncthreads();

    // ---- Q fragments to registers ----
    uint32_t qh[4][4], ql[4][4];
    #pragma unroll
    for (int ks = 0; ks < 4; ks++) {
        uint32_t addr = smb + kAStage + (wid * 16 + (lane & 15)) * kARS
                      + ks * 32 + (lane >> 4) * 16;
        ldsm_x4(qh[ks][0], qh[ks][1], qh[ks][2], qh[ks][3], addr);
        ldsm_x4(ql[ks][0], ql[ks][1], ql[ks][2], ql[ks][3], addr + 128 * kARS);
    }
    __syncthreads();    // stage1 free for kv prefetch

    float m0 = -1e30f, m1 = -1e30f, l0 = 0.f, l1 = 0.f;
    float o[8][4];
    #pragma unroll
    for (int g = 0; g < 8; g++)
        #pragma unroll
        for (int d = 0; d < 4; d++) o[g][d] = 0.f;

    const int ktmax = 2 * qt + 2;
    for (int kt = 0; kt < ktmax; kt++) {
        if (kt + 1 < ktmax) {
            fill_kv(smb + ((kt + 1) & 1) * kAStage, b, h, (kt + 1) * 64);
            CP_COMMIT();
            CP_WAIT(1);
        } else {
            CP_WAIT(0);
        }
        __syncthreads();

        const int kbase = kt * 64;
        if (kbase <= wr0 + 15) {
            const uint32_t st = smb + (kt & 1) * kAStage;

            // ---- S = Q K^T (3-pass) ----
            float s[8][4];
            #pragma unroll
            for (int j = 0; j < 8; j++)
                #pragma unroll
                for (int d = 0; d < 4; d++) s[j][d] = 0.f;

            #pragma unroll
            for (int ks = 0; ks < 4; ks++) {
                #pragma unroll
                for (int ng = 0; ng < 4; ng++) {
                    uint32_t a = st + (ng * 16 + (lane & 7) + (lane >> 4) * 8) * kARS
                               + ks * 32 + ((lane >> 3) & 1) * 16;
                    uint32_t k0, k1, k2, k3, e0, e1, e2, e3;
                    ldsm_x4(k0, k1, k2, k3, a);
                    ldsm_x4(e0, e1, e2, e3, a + kAPlane);
                    mma16816(s[2*ng],   qh[ks], k0, k1);
                    mma16816(s[2*ng],   qh[ks], e0, e1);
                    mma16816(s[2*ng],   ql[ks], k0, k1);
                    mma16816(s[2*ng+1], qh[ks], k2, k3);
                    mma16816(s[2*ng+1], qh[ks], e2, e3);
                    mma16816(s[2*ng+1], ql[ks], k2, k3);
                }
            }

            // ---- mask (straddling tiles only) ----
            const int r0 = wr0 + (lane >> 2), r1 = r0 + 8;
            if (kbase + 63 > wr0) {
                #pragma unroll
                for (int j = 0; j < 8; j++) {
                    int c = kbase + j * 8 + (lane & 3) * 2;
                    if (c > r0)     s[j][0] = -1e30f;
                    if (c + 1 > r0) s[j][1] = -1e30f;
                    if (c > r1)     s[j][2] = -1e30f;
                    if (c + 1 > r1) s[j][3] = -1e30f;
                }
            }

            // ---- online softmax ----
            float rm0 = -1e30f, rm1 = -1e30f;
            #pragma unroll
            for (int j = 0; j < 8; j++) {
                rm0 = fmaxf(rm0, fmaxf(s[j][0], s[j][1]));
                rm1 = fmaxf(rm1, fmaxf(s[j][2], s[j][3]));
            }
            rm0 = fmaxf(rm0, __shfl_xor_sync(0xffffffffu, rm0, 1));
            rm0 = fmaxf(rm0, __shfl_xor_sync(0xffffffffu, rm0, 2));
            rm1 = fmaxf(rm1, __shfl_xor_sync(0xffffffffu, rm1, 1));
            rm1 = fmaxf(rm1, __shfl_xor_sync(0xffffffffu, rm1, 2));
            float mn0 = fmaxf(m0, rm0), mn1 = fmaxf(m1, rm1);
            float cr0 = __expf(m0 - mn0), cr1 = __expf(m1 - mn1);
            m0 = mn0; m1 = mn1;
            float ps0 = 0.f, ps1 = 0.f;
            #pragma unroll
            for (int j = 0; j < 8; j++) {
                s[j][0] = __expf(s[j][0] - m0);
                s[j][1] = __expf(s[j][1] - m0);
                s[j][2] = __expf(s[j][2] - m1);
                s[j][3] = __expf(s[j][3] - m1);
                ps0 += s[j][0] + s[j][1];
                ps1 += s[j][2] + s[j][3];
            }
            ps0 += __shfl_xor_sync(0xffffffffu, ps0, 1);
            ps0 += __shfl_xor_sync(0xffffffffu, ps0, 2);
            ps1 += __shfl_xor_sync(0xffffffffu, ps1, 1);
            ps1 += __shfl_xor_sync(0xffffffffu, ps1, 2);
            l0 = l0 * cr0 + ps0;
            l1 = l1 * cr1 + ps1;
            #pragma unroll
            for (int g = 0; g < 8; g++) {
                o[g][0] *= cr0; o[g][1] *= cr0;
                o[g][2] *= cr1; o[g][3] *= cr1;
            }

            // ---- O += P V (3-pass, P repacked in registers) ----
            #pragma unroll
            for (int t = 0; t < 4; t++) {
                uint32_t ph[4], pl[4];
                split2(s[2*t][0],   s[2*t][1],   ph[0], pl[0]);
                split2(s[2*t][2],   s[2*t][3],   ph[1], pl[1]);
                split2(s[2*t+1][0], s[2*t+1][1], ph[2], pl[2]);
                split2(s[2*t+1][2], s[2*t+1][3], ph[3], pl[3]);
                #pragma unroll
                for (int dg = 0; dg < 4; dg++) {
                    uint32_t a = st + 2 * kAPlane
                               + (t * 16 + (lane & 7) + ((lane >> 3) & 1) * 8) * kARS
                               + dg * 32 + (lane >> 4) * 16;
                    uint32_t v0, v1, v2, v3, w0, w1, w2, w3;
                    ldsm_x4_t(v0, v1, v2, v3, a);
                    ldsm_x4_t(w0, w1, w2, w3, a + kAPlane);
                    mma16816(o[2*dg],   ph, v0, v1);
                    mma16816(o[2*dg],   ph, w0, w1);
                    mma16816(o[2*dg],   pl, v0, v1);
                    mma16816(o[2*dg+1], ph, v2, v3);
                    mma16816(o[2*dg+1], ph, w2, w3);
                    mma16816(o[2*dg+1], pl, v2, v3);
                }
            }
        }
        __syncthreads();
    }

    // ---- epilogue: O/l -> bf16 hi/lo planes ----
    const float inv0 = 1.f / l0, inv1 = 1.f / l1;
    const size_t tok0 = (size_t)(b * kT) + wr0 + (lane >> 2);
    #pragma unroll
    for (int g = 0; g < 8; g++) {
        int col = h * 64 + g * 8 + (lane & 3) * 2;
        uint32_t hh, ll;
        split2(o[g][0] * inv0, o[g][1] * inv0, hh, ll);
        *reinterpret_cast<uint32_t*>(g_ab_h + tok0 * kD + col) = hh;
        *reinterpret_cast<uint32_t*>(g_ab_l + tok0 * kD + col) = ll;
        split2(o[g][2] * inv1, o[g][3] * inv1, hh, ll);
        *reinterpret_cast<uint32_t*>(g_ab_h + (tok0 + 8) * kD + col) = hh;
        *reinterpret_cast<uint32_t*>(g_ab_l + (tok0 + 8) * kD + col) = ll;
    }
}

// ---------------- conversion kernels ----------------
__global__ void convert_x(const float* __restrict__ x)
{
    int i = blockIdx.x * 256 + threadIdx.x;
    float4 v = ((const float4*)x)[i];
    size_t o = (size_t)i * 4;
    float a[4] = {v.x, v.y, v.z, v.w};
    #pragma unroll
    for (int j = 0; j < 4; j++) {
        __nv_bfloat16 h = __float2bfloat16_rn(a[j]);
        g_xb_h[o + j] = h;
        g_xb_l[o + j] = __float2bfloat16_rn(a[j] - __bfloat162float(h));
    }
}

__device__ __forceinline__ void transpose_body(
    const float* __restrict__ src, __nv_bfloat16* __restrict__ hi,
    __nv_bfloat16* __restrict__ lo, int K, int N)
{
    __shared__ float tile[32][33];
    int bn = blockIdx.x * 32, bk = blockIdx.y * 32;
    int tx = threadIdx.x, ty = threadIdx.y;
    #pragma unroll
    for (int i = 0; i < 32; i += 8)
        tile[ty + i][tx] = src[(size_t)(bk + ty + i) * N + bn + tx];
    __syncthreads();
    #pragma unroll
    for (int i = 0; i < 32; i += 8) {
        float v = tile[tx][ty + i];
        __nv_bfloat16 h = __float2bfloat16_rn(v);
        size_t o = (size_t)(bn + ty + i) * K + bk + tx;
        hi[o] = h;
        lo[o] = __float2bfloat16_rn(v - __bfloat162float(h));
    }
}

__global__ void transpose_qkvo(const float* Wq, const float* Wk, const float* Wv, const float* Wo)
{
    int z = blockIdx.z;
    const float* src = (z == 0) ? Wq : (z == 1) ? Wk : (z == 2) ? Wv : Wo;
    transpose_body(src, g_w4t_h + (size_t)z * kD * kD, g_w4t_l + (size_t)z * kD * kD, kD, kD);
}

__global__ void transpose_w1(const float* W1e)
{
    int e = blockIdx.z;
    size_t off = (size_t)e * kD * kFF;
    transpose_body(W1e + off, g_w1t_h + off, g_w1t_l + off, kD, kFF);
}

__global__ void transpose_w2(const float* W2e)
{
    int e = blockIdx.z;
    size_t off = (size_t)e * kFF * kD;
    transpose_body(W2e + off, g_w2t_h + off, g_w2t_l + off, kFF, kD);
}

// ---------------- add + layernorm ----------------
__device__ __forceinline__ float block_sum_256(float v, float* red)
{
    int tid = threadIdx.x;
    #pragma unroll
    for (int o = 16; o; o >>= 1) v += __shfl_xor_sync(0xffffffffu, v, o);
    if ((tid & 31) == 0) red[tid >> 5] = v;
    __syncthreads();
    if (tid < 8) {
        float x = red[tid];
        #pragma unroll
        for (int o = 4; o; o >>= 1) x += __shfl_xor_sync(0xffu, x, o);
        if (tid == 0) red[0] = x;
    }
    __syncthreads();
    float r = red[0];
    __syncthreads();
    return r;
}

__device__ __forceinline__ void add_ln_body(
    const float* __restrict__ A, const float* __restrict__ Bb,
    const float* __restrict__ gw, const float* __restrict__ bw,
    float* __restrict__ out, __nv_bfloat16* __restrict__ oh,
    __nv_bfloat16* __restrict__ ol)
{
    __shared__ float red[8];
    int t = blockIdx.x, tid = threadIdx.x;
    float4 av = ((const float4*)(A  + (size_t)t * kD))[tid];
    float4 bv = ((const float4*)(Bb + (size_t)t * kD))[tid];
    float vx = av.x + bv.x, vy = av.y + bv.y, vz = av.z + bv.z, vw = av.w + bv.w;
    float ssum = block_sum_256(vx + vy + vz + vw, red);
    float mu = ssum * (1.0f / kD);
    float dx = vx - mu, dy = vy - mu, dz = vz - mu, dw = vw - mu;
    float sq = block_sum_256(dx*dx + dy*dy + dz*dz + dw*dw, red);
    float rstd = rsqrtf(sq * (1.0f / kD) + kEPS);
    float4 gv = ((const float4*)gw)[tid];
    float4 be = ((const float4*)bw)[tid];
    float ovv[4] = {dx*rstd*gv.x + be.x, dy*rstd*gv.y + be.y,
                    dz*rstd*gv.z + be.z, dw*rstd*gv.w + be.w};
    ((float4*)(out + (size_t)t * kD))[tid] = make_float4(ovv[0], ovv[1], ovv[2], ovv[3]);
    if (oh) {
        size_t o = (size_t)t * kD + tid * 4;
        #pragma unroll
        for (int j = 0; j < 4; j++) {
            __nv_bfloat16 h = __float2bfloat16_rn(ovv[j]);
            oh[o + j] = h;
            ol[o + j] = __float2bfloat16_rn(ovv[j] - __bfloat162float(h));
        }
    }
}

__global__ void ln1_kernel(const float* __restrict__ x,
                           const float* __restrict__ g, const float* __restrict__ b)
{
    add_ln_body(x, g_proj, g, b, g_x1, g_x1b_h, g_x1b_l);
}

__global__ void ln2_kernel(const float* __restrict__ g, const float* __restrict__ b,
                           float* __restrict__ out)
{
    add_ln_body(g_x1, g_y, g, b, out, nullptr, nullptr);
}

// ---------------- MoE gate (top-1 argmax) ----------------
__global__ void zero_cnt()
{
    if (threadIdx.x < kE) g_cnt[threadIdx.x] = 0;
}

__global__ void gate_kernel(const float* __restrict__ Wg, const float* __restrict__ bg)
{
    int t = blockIdx.x, tid = threadIdx.x;
    float a0 = 0.f, a1 = 0.f, a2 = 0.f, a3 = 0.f;
    const float* xr = g_x1 + (size_t)t * kD;
    for (int d = tid; d < kD; d += 128) {
        float xv = xr[d];
        float4 w = ((const float4*)Wg)[d];
        a0 = fmaf(xv, w.x, a0);
        a1 = fmaf(xv, w.y, a1);
        a2 = fmaf(xv, w.z, a2);
        a3 = fmaf(xv, w.w, a3);
    }
    __shared__ float rsm[4][128];
    rsm[0][tid] = a0; rsm[1][tid] = a1; rsm[2][tid] = a2; rsm[3][tid] = a3;
    __syncthreads();
    for (int s = 64; s > 0; s >>= 1) {
        if (tid < s) {
            #pragma unroll
            for (int e = 0; e < 4; e++) rsm[e][tid] += rsm[e][tid + s];
        }
        __syncthreads();
    }
    if (tid == 0) {
        float sc[4];
        #pragma unroll
        for (int e = 0; e < 4; e++) sc[e] = rsm[e][0] + bg[e];
        int best = 0; float bvv = sc[0];
        #pragma unroll
        for (int e = 1; e < 4; e++) {
            if (sc[e] > bvv) { bvv = sc[e]; best = e; }
        }
        int pos = atomicAdd(&g_cnt[best], 1);
        g_list[best * kNT + pos] = t;
    }
}

// ---------------- launch ----------------
extern "C" void kernel_launch(void* const* d_in, const int* in_sizes, int n_in,
                              void* d_out, int out_size)
{
    const float* x    = (const float*)d_in[0];
    const float* Wq   = (const float*)d_in[2];
    const float* bq   = (const float*)d_in[3];
    const float* Wk   = (const float*)d_in[4];
    const float* bk   = (const float*)d_in[5];
    const float* Wv   = (const float*)d_in[6];
    const float* bv   = (const float*)d_in[7];
    const float* Wo   = (const float*)d_in[8];
    const float* bo   = (const float*)d_in[9];
    const float* ln1g = (const float*)d_in[10];
    const float* ln1b = (const float*)d_in[11];
    const float* Wg   = (const float*)d_in[12];
    const float* bg   = (const float*)d_in[13];
    const float* W1e  = (const float*)d_in[14];
    const float* b1e  = (const float*)d_in[15];
    const float* W2e  = (const float*)d_in[16];
    const float* b2e  = (const float*)d_in[17];
    const float* ln2g = (const float*)d_in[18];
    const float* ln2b = (const float*)d_in[19];
    float* out = (float*)d_out;

    cudaFuncSetAttribute(attn_tc, cudaFuncAttributeMaxDynamicSharedMemorySize, ATTN_SMEM);
    cudaFuncSetAttribute(qkv_tc,  cudaFuncAttributeMaxDynamicSharedMemorySize, GEMM_SMEM);
    cudaFuncSetAttribute(proj_tc, cudaFuncAttributeMaxDynamicSharedMemorySize, GEMM_SMEM);
    cudaFuncSetAttribute(moe1_tc, cudaFuncAttributeMaxDynamicSharedMemorySize, GEMM_SMEM);
    cudaFuncSetAttribute(moe2_tc, cudaFuncAttributeMaxDynamicSharedMemorySize, GEMM_SMEM);

    // weight/activation prep
    convert_x<<<kNT * kD / 4 / 256, 256>>>(x);
    transpose_qkvo<<<dim3(kD/32, kD/32, 4), dim3(32, 8)>>>(Wq, Wk, Wv, Wo);
    transpose_w1<<<dim3(kFF/32, kD/32, kE), dim3(32, 8)>>>(W1e);
    transpose_w2<<<dim3(kD/32, kFF/32, kE), dim3(32, 8)>>>(W2e);

    // attention path
    qkv_tc<<<dim3(kD/128, kNT/128, 3), 256, GEMM_SMEM>>>(bq, bk, bv);
    attn_tc<<<dim3(kT/128, kB*kH), 256, ATTN_SMEM>>>();
    proj_tc<<<dim3(kD/128, kNT/128), 256, GEMM_SMEM>>>(bo);
    ln1_kernel<<<kNT, 256>>>(x, ln1g, ln1b);

    // MoE path
    zero_cnt<<<1, 32>>>();
    gate_kernel<<<kNT, 128>>>(Wg, bg);
    moe1_tc<<<dim3(kFF/128, kNT/128, kE), 256, GEMM_SMEM>>>(b1e);
    moe2_tc<<<dim3(kD/128, kNT/128, kE), 256, GEMM_SMEM>>>(b2e);
    ln2_kernel<<<kNT, 256>>>(ln2g, ln2b, out);
}